// round 4
// baseline (speedup 1.0000x reference)
#include <cuda_runtime.h>
#include <cstdint>

// Problem constants (fixed by the reference)
#define NU  100000
#define NI  40000
#define NN  140000            // NU + NI
#define H   32
#define IND 128
#define NE  1200000
#define NDIR (2 * NE)         // directed edges (both orientations)

// Packed CSR entry: neighbor id + edge weight (8 bytes, one LDG.64)
struct __align__(8) Ent { int n; float w; };

// Scratch: device globals (allocation-free contract).
__device__ float g_x0[(size_t)NN * H];   // projection output
__device__ float g_x1[(size_t)NN * H];   // layer-1 output
__device__ int   g_deg[NN];
__device__ float g_dinv[NN];
__device__ int   g_off[NN + 1];          // CSR row offsets
__device__ int   g_cur[NN];              // build cursors
__device__ Ent   g_ent[NDIR];            // packed CSR (neighbor, weight)

// ---------------------------------------------------------------------------
__global__ void k_zero_deg() {
    int t = blockIdx.x * blockDim.x + threadIdx.x;
    if (t < NN) g_deg[t] = 0;
}

// Degree count (matches segment_sum(ones, dst), symmetric bipartite edges)
__global__ void k_count_deg(const int* __restrict__ eu, const int* __restrict__ ei) {
    int t = blockIdx.x * blockDim.x + threadIdx.x;
    if (t < NE) {
        atomicAdd(&g_deg[eu[t]], 1);
        atomicAdd(&g_deg[NU + ei[t]], 1);
    }
}

__global__ void k_dinv() {
    int t = blockIdx.x * blockDim.x + threadIdx.x;
    if (t < NN) {
        int d = g_deg[t];
        g_dinv[t] = (d > 0) ? rsqrtf((float)d) : 0.0f;
    }
}

// ---------------------------------------------------------------------------
// Exclusive prefix sum of g_deg -> g_off (and init cursors). Single block.
// Each thread scans a contiguous chunk; Hillis-Steele over 1024 partials.
// ---------------------------------------------------------------------------
__global__ void k_scan() {
    __shared__ int partial[1024];
    const int T = 1024;
    const int tid = threadIdx.x;
    const int chunk = (NN + T - 1) / T;            // 137
    const int start = tid * chunk;
    const int end   = (start + chunk < NN) ? start + chunk : NN;

    int sum = 0;
    for (int i = start; i < end; i++) sum += g_deg[i];
    partial[tid] = sum;
    __syncthreads();

    for (int d = 1; d < T; d <<= 1) {
        int v = (tid >= d) ? partial[tid - d] : 0;
        __syncthreads();
        partial[tid] += v;
        __syncthreads();
    }

    int run = (tid > 0) ? partial[tid - 1] : 0;    // exclusive base
    for (int i = start; i < end; i++) {
        g_off[i] = run;
        g_cur[i] = run;
        run += g_deg[i];
    }
    if (tid == T - 1) g_off[NN] = run;             // == 2*NE
}

// ---------------------------------------------------------------------------
// CSR build: each undirected edge (u, i) inserts both directions.
// atomicAdd on cursors reserves unique slots; one STG.64 per direction.
// ---------------------------------------------------------------------------
__global__ void k_build(const int* __restrict__ eu, const int* __restrict__ ei) {
    int t = blockIdx.x * blockDim.x + threadIdx.x;
    if (t < NE) {
        const int u  = eu[t];
        const int it = NU + ei[t];
        const float w = g_dinv[u] * g_dinv[it];
        int pu = atomicAdd(&g_cur[u], 1);
        g_ent[pu] = Ent{it, w};
        int pi = atomicAdd(&g_cur[it], 1);
        g_ent[pi] = Ent{u, w};
    }
}

// ---------------------------------------------------------------------------
// TypeProjector: out[row, :] = x[row, :128] @ W[128,32] + b.
// One warp per row; W staged in shared (16KB), row staged in shared (per-warp).
// ---------------------------------------------------------------------------
__global__ void k_project(const float* __restrict__ x, const float* __restrict__ Wm,
                          const float* __restrict__ b, int row_offset, int rows) {
    __shared__ float Ws[IND * H];
    __shared__ float xs[8][IND];
    for (int i = threadIdx.x; i < IND * H; i += blockDim.x) Ws[i] = Wm[i];
    __syncthreads();

    const int warp = threadIdx.x >> 5;
    const int lane = threadIdx.x & 31;
    const float bias = b[lane];

    int row = blockIdx.x * 8 + warp;
    if (row < rows) {
        float4 v = reinterpret_cast<const float4*>(x + (size_t)row * IND)[lane];
        reinterpret_cast<float4*>(xs[warp])[lane] = v;
        __syncwarp();
        float acc = bias;
        #pragma unroll
        for (int k = 0; k < IND; k++)
            acc = fmaf(xs[warp][k], Ws[k * H + lane], acc);
        g_x0[(size_t)(row_offset + row) * H + lane] = acc;
    }
}

// ---------------------------------------------------------------------------
// Gather body: acc = sum_{j in [s,e)} ent[j].w * xin[ent[j].n * H + lane].
// 8-way unroll -> MLP ~8 on the random 128B row loads (L2-resident),
// dropping effective latency below the issue floor. Entry loads are
// lane-uniform LDG.64 broadcasts.
// ---------------------------------------------------------------------------
__device__ __forceinline__ float gather_row(const float* __restrict__ xin,
                                            int s, int e, int lane) {
    float acc = 0.0f;
    int j = s;
    for (; j + 8 <= e; j += 8) {
        Ent t0 = g_ent[j],     t1 = g_ent[j + 1];
        Ent t2 = g_ent[j + 2], t3 = g_ent[j + 3];
        Ent t4 = g_ent[j + 4], t5 = g_ent[j + 5];
        Ent t6 = g_ent[j + 6], t7 = g_ent[j + 7];
        const float v0 = xin[(size_t)t0.n * H + lane];
        const float v1 = xin[(size_t)t1.n * H + lane];
        const float v2 = xin[(size_t)t2.n * H + lane];
        const float v3 = xin[(size_t)t3.n * H + lane];
        const float v4 = xin[(size_t)t4.n * H + lane];
        const float v5 = xin[(size_t)t5.n * H + lane];
        const float v6 = xin[(size_t)t6.n * H + lane];
        const float v7 = xin[(size_t)t7.n * H + lane];
        acc = fmaf(t0.w, v0, acc); acc = fmaf(t1.w, v1, acc);
        acc = fmaf(t2.w, v2, acc); acc = fmaf(t3.w, v3, acc);
        acc = fmaf(t4.w, v4, acc); acc = fmaf(t5.w, v5, acc);
        acc = fmaf(t6.w, v6, acc); acc = fmaf(t7.w, v7, acc);
    }
    for (; j < e; j++) {
        Ent t = g_ent[j];
        acc = fmaf(t.w, xin[(size_t)t.n * H + lane], acc);
    }
    return acc;
}

// Layer 1: x1[v] = sum_{n in N(v)} w * x0[n]. One warp per node, lane = column.
__global__ void __launch_bounds__(256) k_gather1() {
    const int v = blockIdx.x * (blockDim.x >> 5) + (threadIdx.x >> 5);
    if (v >= NN) return;
    const int lane = threadIdx.x & 31;
    const float acc = gather_row(g_x0, g_off[v], g_off[v + 1], lane);
    g_x1[(size_t)v * H + lane] = acc;
}

// Layer 2 + fused mean epilogue: out[v] = (x0[v] + x1[v] + gather(x1))/3.
__global__ void __launch_bounds__(256) k_gather2(float* __restrict__ out) {
    const int v = blockIdx.x * (blockDim.x >> 5) + (threadIdx.x >> 5);
    if (v >= NN) return;
    const int lane = threadIdx.x & 31;
    const float acc = gather_row(g_x1, g_off[v], g_off[v + 1], lane);
    const size_t idx = (size_t)v * H + lane;
    out[idx] = (g_x0[idx] + g_x1[idx] + acc) * (1.0f / 3.0f);
}

extern "C" void kernel_launch(void* const* d_in, const int* in_sizes, int n_in,
                              void* d_out, int out_size) {
    const float* x_user = (const float*)d_in[0];
    const float* x_item = (const float*)d_in[1];
    const int*   eu     = (const int*)  d_in[2];
    const int*   ei     = (const int*)  d_in[3];
    const float* Wu     = (const float*)d_in[4];
    const float* bu     = (const float*)d_in[5];
    const float* Wi     = (const float*)d_in[6];
    const float* bi     = (const float*)d_in[7];
    float* out = (float*)d_out;

    const int B = 256;

    // Graph preprocessing: degree -> dinv -> offsets -> packed CSR
    k_zero_deg<<<(NN + B - 1) / B, B>>>();
    k_count_deg<<<(NE + B - 1) / B, B>>>(eu, ei);
    k_dinv<<<(NN + B - 1) / B, B>>>();
    k_scan<<<1, 1024>>>();
    k_build<<<(NE + B - 1) / B, B>>>(eu, ei);

    // Per-type projection into g_x0 (users first, then items)
    k_project<<<NU / 8, B>>>(x_user, Wu, bu, 0,  NU);
    k_project<<<NI / 8, B>>>(x_item, Wi, bi, NU, NI);

    // Two gather-only LGConv layers (layer 2 fused with mean epilogue)
    const int warps_per_block = B / 32;
    const int gather_blocks = (NN + warps_per_block - 1) / warps_per_block;
    k_gather1<<<gather_blocks, B>>>();
    k_gather2<<<gather_blocks, B>>>(out);
}

// round 5
// speedup vs baseline: 1.6929x; 1.6929x over previous
#include <cuda_runtime.h>
#include <cstdint>

// Problem constants (fixed by the reference)
#define NU  100000
#define NI  40000
#define NN  140000            // NU + NI
#define H   32
#define IND 128
#define NE  1200000
#define NDIR (2 * NE)         // directed edges (both orientations)

#define SCAN_T 256
#define SCAN_B ((NN + SCAN_T - 1) / SCAN_T)   // 547

// Packed CSR entry: neighbor id + edge weight (8 bytes, one LDG.64)
struct __align__(8) Ent { int n; float w; };

// Scratch: device globals (allocation-free contract).
__device__ float g_x0[(size_t)NN * H];   // projection output
__device__ float g_x1[(size_t)NN * H];   // layer-1 output
__device__ int   g_deg[NN];
__device__ float g_dinv[NN];
__device__ int   g_off[NN + 1];          // CSR row offsets
__device__ int   g_cur[NN];              // build cursors
__device__ Ent   g_ent[NDIR];            // packed CSR (neighbor, weight)
__device__ int   g_bsum[SCAN_B];         // per-block degree sums
__device__ int   g_bbase[SCAN_B];        // exclusive block bases

// ---------------------------------------------------------------------------
__global__ void k_zero_deg() {
    int t = blockIdx.x * blockDim.x + threadIdx.x;
    if (t < NN) g_deg[t] = 0;
}

// Degree count (matches segment_sum(ones, dst), symmetric bipartite edges)
__global__ void k_count_deg(const int* __restrict__ eu, const int* __restrict__ ei) {
    int t = blockIdx.x * blockDim.x + threadIdx.x;
    if (t < NE) {
        atomicAdd(&g_deg[eu[t]], 1);
        atomicAdd(&g_deg[NU + ei[t]], 1);
    }
}

__global__ void k_dinv() {
    int t = blockIdx.x * blockDim.x + threadIdx.x;
    if (t < NN) {
        int d = g_deg[t];
        g_dinv[t] = (d > 0) ? rsqrtf((float)d) : 0.0f;
    }
}

// ---------------------------------------------------------------------------
// 3-phase grid-wide exclusive scan of g_deg -> g_off (+ cursors).
// p1: per-block reduce; p2: single-block scan of 547 block sums;
// p3: per-block local scan + base add-back.
// ---------------------------------------------------------------------------
__global__ void k_scan_p1() {
    __shared__ int sh[SCAN_T];
    const int i = blockIdx.x * SCAN_T + threadIdx.x;
    sh[threadIdx.x] = (i < NN) ? g_deg[i] : 0;
    __syncthreads();
    for (int d = SCAN_T / 2; d > 0; d >>= 1) {
        if (threadIdx.x < d) sh[threadIdx.x] += sh[threadIdx.x + d];
        __syncthreads();
    }
    if (threadIdx.x == 0) g_bsum[blockIdx.x] = sh[0];
}

__global__ void k_scan_p2() {
    __shared__ int sh[1024];
    const int tid = threadIdx.x;
    const int v = (tid < SCAN_B) ? g_bsum[tid] : 0;
    sh[tid] = v;
    __syncthreads();
    for (int d = 1; d < 1024; d <<= 1) {
        int t = (tid >= d) ? sh[tid - d] : 0;
        __syncthreads();
        sh[tid] += t;
        __syncthreads();
    }
    if (tid < SCAN_B) g_bbase[tid] = sh[tid] - v;   // exclusive base
}

__global__ void k_scan_p3() {
    __shared__ int sh[SCAN_T];
    const int i = blockIdx.x * SCAN_T + threadIdx.x;
    const int v = (i < NN) ? g_deg[i] : 0;
    sh[threadIdx.x] = v;
    __syncthreads();
    for (int d = 1; d < SCAN_T; d <<= 1) {
        int t = (threadIdx.x >= d) ? sh[threadIdx.x - d] : 0;
        __syncthreads();
        sh[threadIdx.x] += t;
        __syncthreads();
    }
    const int incl = sh[threadIdx.x];
    const int base = g_bbase[blockIdx.x];
    if (i < NN) {
        const int off = base + incl - v;            // exclusive
        g_off[i] = off;
        g_cur[i] = off;
    }
    if (i == NN - 1) g_off[NN] = base + incl;       // == 2*NE
}

// ---------------------------------------------------------------------------
// CSR build: each undirected edge (u, i) inserts both directions.
// atomicAdd on cursors reserves unique slots; one STG.64 per direction.
// ---------------------------------------------------------------------------
__global__ void k_build(const int* __restrict__ eu, const int* __restrict__ ei) {
    int t = blockIdx.x * blockDim.x + threadIdx.x;
    if (t < NE) {
        const int u  = eu[t];
        const int it = NU + ei[t];
        const float w = g_dinv[u] * g_dinv[it];
        int pu = atomicAdd(&g_cur[u], 1);
        g_ent[pu] = Ent{it, w};
        int pi = atomicAdd(&g_cur[it], 1);
        g_ent[pi] = Ent{u, w};
    }
}

// ---------------------------------------------------------------------------
// TypeProjector: out[row, :] = x[row, :128] @ W[128,32] + b.
// One warp per row; W staged in shared (16KB), row staged in shared (per-warp).
// ---------------------------------------------------------------------------
__global__ void k_project(const float* __restrict__ x, const float* __restrict__ Wm,
                          const float* __restrict__ b, int row_offset, int rows) {
    __shared__ float Ws[IND * H];
    __shared__ float xs[8][IND];
    for (int i = threadIdx.x; i < IND * H; i += blockDim.x) Ws[i] = Wm[i];
    __syncthreads();

    const int warp = threadIdx.x >> 5;
    const int lane = threadIdx.x & 31;
    const float bias = b[lane];

    int row = blockIdx.x * 8 + warp;
    if (row < rows) {
        float4 v = reinterpret_cast<const float4*>(x + (size_t)row * IND)[lane];
        reinterpret_cast<float4*>(xs[warp])[lane] = v;
        __syncwarp();
        float acc = bias;
        #pragma unroll
        for (int k = 0; k < IND; k++)
            acc = fmaf(xs[warp][k], Ws[k * H + lane], acc);
        g_x0[(size_t)(row_offset + row) * H + lane] = acc;
    }
}

// ---------------------------------------------------------------------------
// Gather body: acc = sum_{j in [s,e)} ent[j].w * xin[ent[j].n * H + lane].
// 8-way unroll -> MLP ~8 on the random 128B row loads (L2-resident).
// Entry loads are lane-uniform LDG.64 broadcasts.
// ---------------------------------------------------------------------------
__device__ __forceinline__ float gather_row(const float* __restrict__ xin,
                                            int s, int e, int lane) {
    float acc = 0.0f;
    int j = s;
    for (; j + 8 <= e; j += 8) {
        Ent t0 = g_ent[j],     t1 = g_ent[j + 1];
        Ent t2 = g_ent[j + 2], t3 = g_ent[j + 3];
        Ent t4 = g_ent[j + 4], t5 = g_ent[j + 5];
        Ent t6 = g_ent[j + 6], t7 = g_ent[j + 7];
        const float v0 = xin[(size_t)t0.n * H + lane];
        const float v1 = xin[(size_t)t1.n * H + lane];
        const float v2 = xin[(size_t)t2.n * H + lane];
        const float v3 = xin[(size_t)t3.n * H + lane];
        const float v4 = xin[(size_t)t4.n * H + lane];
        const float v5 = xin[(size_t)t5.n * H + lane];
        const float v6 = xin[(size_t)t6.n * H + lane];
        const float v7 = xin[(size_t)t7.n * H + lane];
        acc = fmaf(t0.w, v0, acc); acc = fmaf(t1.w, v1, acc);
        acc = fmaf(t2.w, v2, acc); acc = fmaf(t3.w, v3, acc);
        acc = fmaf(t4.w, v4, acc); acc = fmaf(t5.w, v5, acc);
        acc = fmaf(t6.w, v6, acc); acc = fmaf(t7.w, v7, acc);
    }
    for (; j < e; j++) {
        Ent t = g_ent[j];
        acc = fmaf(t.w, xin[(size_t)t.n * H + lane], acc);
    }
    return acc;
}

// Layer 1: x1[v] = sum_{n in N(v)} w * x0[n]. One warp per node, lane = column.
__global__ void __launch_bounds__(256) k_gather1() {
    const int v = blockIdx.x * (blockDim.x >> 5) + (threadIdx.x >> 5);
    if (v >= NN) return;
    const int lane = threadIdx.x & 31;
    const float acc = gather_row(g_x0, g_off[v], g_off[v + 1], lane);
    g_x1[(size_t)v * H + lane] = acc;
}

// Layer 2 + fused mean epilogue: out[v] = (x0[v] + x1[v] + gather(x1))/3.
__global__ void __launch_bounds__(256) k_gather2(float* __restrict__ out) {
    const int v = blockIdx.x * (blockDim.x >> 5) + (threadIdx.x >> 5);
    if (v >= NN) return;
    const int lane = threadIdx.x & 31;
    const float acc = gather_row(g_x1, g_off[v], g_off[v + 1], lane);
    const size_t idx = (size_t)v * H + lane;
    out[idx] = (g_x0[idx] + g_x1[idx] + acc) * (1.0f / 3.0f);
}

extern "C" void kernel_launch(void* const* d_in, const int* in_sizes, int n_in,
                              void* d_out, int out_size) {
    const float* x_user = (const float*)d_in[0];
    const float* x_item = (const float*)d_in[1];
    const int*   eu     = (const int*)  d_in[2];
    const int*   ei     = (const int*)  d_in[3];
    const float* Wu     = (const float*)d_in[4];
    const float* bu     = (const float*)d_in[5];
    const float* Wi     = (const float*)d_in[6];
    const float* bi     = (const float*)d_in[7];
    float* out = (float*)d_out;

    const int B = 256;

    // Graph preprocessing: degree -> dinv -> offsets (3-phase scan) -> CSR
    k_zero_deg<<<(NN + B - 1) / B, B>>>();
    k_count_deg<<<(NE + B - 1) / B, B>>>(eu, ei);
    k_dinv<<<(NN + B - 1) / B, B>>>();
    k_scan_p1<<<SCAN_B, SCAN_T>>>();
    k_scan_p2<<<1, 1024>>>();
    k_scan_p3<<<SCAN_B, SCAN_T>>>();
    k_build<<<(NE + B - 1) / B, B>>>(eu, ei);

    // Per-type projection into g_x0 (users first, then items)
    k_project<<<NU / 8, B>>>(x_user, Wu, bu, 0,  NU);
    k_project<<<NI / 8, B>>>(x_item, Wi, bi, NU, NI);

    // Two gather-only LGConv layers (layer 2 fused with mean epilogue)
    const int warps_per_block = B / 32;
    const int gather_blocks = (NN + warps_per_block - 1) / warps_per_block;
    k_gather1<<<gather_blocks, B>>>();
    k_gather2<<<gather_blocks, B>>>(out);
}